// round 10
// baseline (speedup 1.0000x reference)
#include <cuda_runtime.h>

// Problem constants (fixed by the reference): B=8, C=64, H=W=256.
#define Bn   8
#define Cn   64
#define Hn   256
#define Wn   256
#define HWn  (Hn * Wn)          // 65536
#define NPIX (Bn * HWn)         // 524288
#define FULLM 0xFFFFFFFFu
#define TPB  256                // 8 independent warps per block

// Warp-autonomous: warp = 32 consecutive pixels x ALL 64 channels.
// No shared memory, no __syncthreads. Valid-pixel results are stored
// directly (scattered 4B); L2 write-back merges them with the zero quads.
__global__ __launch_bounds__(TPB)
void warp_bilinear_kernel(const float* __restrict__ phi,
                          const float* __restrict__ x_enc,
                          const float* __restrict__ m,
                          float* __restrict__ out)
{
    const int lane  = threadIdx.x & 31;
    const int wid_g = blockIdx.x * (TPB / 32) + (threadIdx.x >> 5); // 0..16383

    const int b   = wid_g >> 11;            // 2048 pixel-warps per batch image
    const int hwg = (wid_g & 2047) << 5;    // base hw of this warp's 32 pixels
    const int hw  = hwg + lane;
    const int h   = hw >> 8;
    const int w   = hw & (Wn - 1);

    // ---- per-lane (per-pixel) sampling setup (identical math throughout) ----
    const float px = phi[(b * 2 + 0) * HWn + hw];
    const float py = phi[(b * 2 + 1) * HWn + hw];
    const float mv = m[b * HWn + hw];

    // vgrid = 2*(coord+phi)/(dim-1) - 1 + 2*phi ; unnormalize (align_corners=False)
    const float vx = 2.0f * ((float)w + px) / (float)(Wn - 1) - 1.0f + 2.0f * px;
    const float vy = 2.0f * ((float)h + py) / (float)(Hn - 1) - 1.0f + 2.0f * py;
    const float ix = (vx + 1.0f) * (0.5f * (float)Wn) - 0.5f;
    const float iy = (vy + 1.0f) * (0.5f * (float)Hn) - 0.5f;

    const float x0f = floorf(ix);
    const float y0f = floorf(iy);
    const int   x0  = (int)x0f;
    const int   y0  = (int)y0f;
    const int   x1  = x0 + 1;
    const int   y1  = y0 + 1;

    const float wx1 = ix - x0f;
    const float wx0 = 1.0f - wx1;
    const float wy1 = iy - y0f;
    const float wy0 = 1.0f - wy1;

    const float vx0 = (x0 >= 0 && x0 < Wn) ? 1.0f : 0.0f;
    const float vx1 = (x1 >= 0 && x1 < Wn) ? 1.0f : 0.0f;
    const float vy0 = (y0 >= 0 && y0 < Hn) ? 1.0f : 0.0f;
    const float vy1 = (y1 >= 0 && y1 < Hn) ? 1.0f : 0.0f;

    // Fold validity AND mask into corner weights (zeros padding, out *= m)
    const float w00 = wy0 * wx0 * vy0 * vx0 * mv;
    const float w01 = wy0 * wx1 * vy0 * vx1 * mv;
    const float w10 = wy1 * wx0 * vy1 * vx0 * mv;
    const float w11 = wy1 * wx1 * vy1 * vx1 * mv;

    const int x0c = min(max(x0, 0), Wn - 1);
    const int x1c = min(max(x1, 0), Wn - 1);
    const int y0c = min(max(y0, 0), Hn - 1);
    const int y1c = min(max(y1, 0), Hn - 1);

    const int o00 = y0c * Wn + x0c;
    const int o01 = y0c * Wn + x1c;
    const int o10 = y1c * Wn + x0c;
    const int o11 = y1c * Wn + x1c;

    const bool pvalid = (w00 != 0.0f) | (w01 != 0.0f) |
                        (w10 != 0.0f) | (w11 != 0.0f);
    const unsigned blt = __ballot_sync(FULLM, pvalid);

    const int baseB = b * Cn * HWn;

    // ---- Phase A: zero stores. Lane owns pixel quad q = 4*(lane&7);
    // round r covers channels 4r + (lane>>3). Quads with a valid pixel
    // zero only their invalid slots (results come from phase B, disjoint). ----
    {
        const int q   = (lane & 7) << 2;
        const int nib = (blt >> q) & 0xF;       // validity of the 4 quad pixels
        const int ch0 = lane >> 3;              // 0..3
        float* __restrict__ oq = out + baseB + hwg + q;
        if (nib == 0) {
            const float4 z = make_float4(0.0f, 0.0f, 0.0f, 0.0f);
#pragma unroll
            for (int r = 0; r < 16; ++r)
                __stcs((float4*)(oq + (ch0 + (r << 2)) * HWn), z);
        } else {
#pragma unroll
            for (int r = 0; r < 16; ++r) {
                float* __restrict__ op = oq + (ch0 + (r << 2)) * HWn;
                if (!(nib & 1)) op[0] = 0.0f;
                if (!(nib & 2)) op[1] = 0.0f;
                if (!(nib & 4)) op[2] = 0.0f;
                if (!(nib & 8)) op[3] = 0.0f;
            }
        }
    }

    // ---- Phase B: parallel gather for valid pixels (k*64 tasks). ----
    if (blt) {  // warp-uniform
        const int k     = __popc(blt);
        const int ntask = k << 6;
        const float* __restrict__ xb = x_enc + baseB;
        for (int t0 = 0; t0 < ntask; t0 += 32) {
            const int  t   = t0 + lane;
            const bool act = t < ntask;
            const int  j   = t >> 6;            // which valid pixel
            const int  ch  = t & 63;
            const int  src = act ? (int)__fns(blt, 0, j + 1) : 0;

            const float W00 = __shfl_sync(FULLM, w00, src);
            const float W01 = __shfl_sync(FULLM, w01, src);
            const float W10 = __shfl_sync(FULLM, w10, src);
            const float W11 = __shfl_sync(FULLM, w11, src);
            const int   O00 = __shfl_sync(FULLM, o00, src);
            const int   O01 = __shfl_sync(FULLM, o01, src);
            const int   O10 = __shfl_sync(FULLM, o10, src);
            const int   O11 = __shfl_sync(FULLM, o11, src);

            const float* __restrict__ pc = xb + ch * HWn;
            float a = 0.0f, bv = 0.0f, cv = 0.0f, dv = 0.0f;
            if (act && W00 != 0.0f) a  = __ldg(pc + O00);
            if (act && W01 != 0.0f) bv = __ldg(pc + O01);
            if (act && W10 != 0.0f) cv = __ldg(pc + O10);
            if (act && W11 != 0.0f) dv = __ldg(pc + O11);
            const float v = fmaf(W00, a, fmaf(W01, bv, fmaf(W10, cv, W11 * dv)));
            if (act) out[baseB + ch * HWn + hwg + src] = v;   // L2 merges
        }
    }
}

extern "C" void kernel_launch(void* const* d_in, const int* in_sizes, int n_in,
                              void* d_out, int out_size)
{
    const float* phi   = (const float*)d_in[0];
    const float* x_enc = (const float*)d_in[1];
    const float* m     = (const float*)d_in[2];
    float* out         = (float*)d_out;

    const int nwarps = NPIX / 32;          // 16384 warp-tiles
    const int blocks = nwarps / (TPB / 32);
    warp_bilinear_kernel<<<blocks, TPB>>>(phi, x_enc, m, out);
}

// round 12
// speedup vs baseline: 1.3816x; 1.3816x over previous
#include <cuda_runtime.h>

// Problem constants (fixed by the reference): B=8, C=64, H=W=256.
#define Bn   8
#define Cn   64
#define Hn   256
#define Wn   256
#define HWn  (Hn * Wn)          // 65536
#define NPIX (Bn * HWn)         // 524288
#define NOUT (Bn * Cn * HWn)    // 33,554,432 floats
#define FULLM 0xFFFFFFFFu
#define TPB  256

// ---------------- K_zero: pure streaming zero-fill (write-only, ~peak BW) ---
#define ZBLK 4096
__global__ __launch_bounds__(TPB)
void k_zero(float4* __restrict__ out4)
{
    const float4 z = make_float4(0.0f, 0.0f, 0.0f, 0.0f);
    const int stride = ZBLK * TPB;                  // 1,048,576
    int i = blockIdx.x * TPB + threadIdx.x;
#pragma unroll
    for (int r = 0; r < (NOUT / 4) / (ZBLK * TPB); ++r, i += stride)
        __stcs(out4 + i, z);
}

// ---------------- K_warp: R7 structure, valid-quad stores only -------------
__global__ __launch_bounds__(TPB)
void k_warp(const float* __restrict__ phi,
            const float* __restrict__ x_enc,
            const float* __restrict__ m,
            float* __restrict__ out)
{
    __shared__ float wgt_s[4][32];      // [corner][rank]
    __shared__ int   off_s[4][32];      // [corner][rank]
    __shared__ int   rank_s[32];        // pixel lane -> rank, -1 if invalid
    __shared__ int   nval_s;
    __shared__ float res_s[32 * 65];    // [rank][channel], pad 65 (bank-safe)

    const int tid   = threadIdx.x;
    const int lane  = tid & 31;
    const int wslot = tid >> 5;

    const int pixwarp = blockIdx.x;          // 0..16383: 32-pixel group
    const int b       = pixwarp >> 11;       // 2048 groups per batch image
    const int hwg     = (pixwarp & 2047) << 5;

    // ---- Phase 1: warp 0 computes sampling setup ONCE for the 32 pixels ----
    if (wslot == 0) {
        const int hw = hwg + lane;
        const int h  = hw >> 8;
        const int w  = hw & (Wn - 1);

        const float px = phi[(b * 2 + 0) * HWn + hw];
        const float py = phi[(b * 2 + 1) * HWn + hw];
        const float mv = m[b * HWn + hw];

        // vgrid = 2*(coord+phi)/(dim-1) - 1 + 2*phi ; unnormalize (align_corners=False)
        const float vx = 2.0f * ((float)w + px) / (float)(Wn - 1) - 1.0f + 2.0f * px;
        const float vy = 2.0f * ((float)h + py) / (float)(Hn - 1) - 1.0f + 2.0f * py;
        const float ix = (vx + 1.0f) * (0.5f * (float)Wn) - 0.5f;
        const float iy = (vy + 1.0f) * (0.5f * (float)Hn) - 0.5f;

        const float x0f = floorf(ix);
        const float y0f = floorf(iy);
        const int   x0  = (int)x0f;
        const int   y0  = (int)y0f;
        const int   x1  = x0 + 1;
        const int   y1  = y0 + 1;

        const float wx1 = ix - x0f;
        const float wx0 = 1.0f - wx1;
        const float wy1 = iy - y0f;
        const float wy0 = 1.0f - wy1;

        const float vx0 = (x0 >= 0 && x0 < Wn) ? 1.0f : 0.0f;
        const float vx1 = (x1 >= 0 && x1 < Wn) ? 1.0f : 0.0f;
        const float vy0 = (y0 >= 0 && y0 < Hn) ? 1.0f : 0.0f;
        const float vy1 = (y1 >= 0 && y1 < Hn) ? 1.0f : 0.0f;

        // Fold validity AND mask into corner weights (zeros padding, out *= m)
        const float w00 = wy0 * wx0 * vy0 * vx0 * mv;
        const float w01 = wy0 * wx1 * vy0 * vx1 * mv;
        const float w10 = wy1 * wx0 * vy1 * vx0 * mv;
        const float w11 = wy1 * wx1 * vy1 * vx1 * mv;

        const int x0c = min(max(x0, 0), Wn - 1);
        const int x1c = min(max(x1, 0), Wn - 1);
        const int y0c = min(max(y0, 0), Hn - 1);
        const int y1c = min(max(y1, 0), Hn - 1);

        const bool pvalid = (w00 != 0.0f) | (w01 != 0.0f) |
                            (w10 != 0.0f) | (w11 != 0.0f);
        const unsigned blt = __ballot_sync(FULLM, pvalid);
        const int rank = __popc(blt & ((1u << lane) - 1u));

        rank_s[lane] = pvalid ? rank : -1;
        if (pvalid) {
            wgt_s[0][rank] = w00;  off_s[0][rank] = y0c * Wn + x0c;
            wgt_s[1][rank] = w01;  off_s[1][rank] = y0c * Wn + x1c;
            wgt_s[2][rank] = w10;  off_s[2][rank] = y1c * Wn + x0c;
            wgt_s[3][rank] = w11;  off_s[3][rank] = y1c * Wn + x1c;
        }
        if (lane == 0) nval_s = __popc(blt);
    }
    __syncthreads();

    const int k = nval_s;
    if (k == 0) return;      // ~31% of blocks: zeros already written by k_zero

    const int baseB = b * Cn * HWn;

    // ---- Phase 2: block-wide gather, task = (valid pixel rank, channel) ----
    {
        const int ntask = k << 6;                 // k * 64 channels
        for (int t = tid; t < ntask; t += TPB) {
            const int j  = t >> 6;                // rank
            const int ch = t & 63;
            const float W00 = wgt_s[0][j];
            const float W01 = wgt_s[1][j];
            const float W10 = wgt_s[2][j];
            const float W11 = wgt_s[3][j];
            const int   O00 = off_s[0][j];
            const int   O01 = off_s[1][j];
            const int   O10 = off_s[2][j];
            const int   O11 = off_s[3][j];
            const float* __restrict__ pc = x_enc + baseB + ch * HWn;
            float a = 0.0f, bv = 0.0f, cv = 0.0f, dv = 0.0f;
            if (W00 != 0.0f) a  = __ldg(pc + O00);
            if (W01 != 0.0f) bv = __ldg(pc + O01);
            if (W10 != 0.0f) cv = __ldg(pc + O10);
            if (W11 != 0.0f) dv = __ldg(pc + O11);
            res_s[j * 65 + ch] =
                fmaf(W00, a, fmaf(W01, bv, fmaf(W10, cv, W11 * dv)));
        }
    }
    __syncthreads();

    // ---- Phase 3: store ONLY quads containing >=1 valid pixel (full 16B,
    // invalid slots written as 0 -- overwrites k_zero's zeros, harmless). ----
    const int q  = (tid & 7) << 2;                // pixel base within group
    const int r0 = rank_s[q + 0];
    const int r1 = rank_s[q + 1];
    const int r2 = rank_s[q + 2];
    const int r3 = rank_s[q + 3];
    // FIXED predicate: true iff ANY rank is valid (>= 0). Previous round
    // used OR of ranks, which is negative if ANY rank is -1 (all-ones).
    if ((r0 >= 0) | (r1 >= 0) | (r2 >= 0) | (r3 >= 0)) {
#pragma unroll
        for (int rd = 0; rd < 2; ++rd) {
            const int ch = (tid >> 3) + (rd << 5);    // 0..63
            float4 v;
            v.x = (r0 >= 0) ? res_s[r0 * 65 + ch] : 0.0f;
            v.y = (r1 >= 0) ? res_s[r1 * 65 + ch] : 0.0f;
            v.z = (r2 >= 0) ? res_s[r2 * 65 + ch] : 0.0f;
            v.w = (r3 >= 0) ? res_s[r3 * 65 + ch] : 0.0f;
            __stcs((float4*)(out + baseB + ch * HWn + hwg + q), v);
        }
    }
}

extern "C" void kernel_launch(void* const* d_in, const int* in_sizes, int n_in,
                              void* d_out, int out_size)
{
    const float* phi   = (const float*)d_in[0];
    const float* x_enc = (const float*)d_in[1];
    const float* m     = (const float*)d_in[2];
    float* out         = (float*)d_out;

    k_zero<<<ZBLK, TPB>>>((float4*)out);
    k_warp<<<(Bn * HWn) / 32, TPB>>>(phi, x_enc, m, out);
}

// round 13
// speedup vs baseline: 1.6016x; 1.1592x over previous
#include <cuda_runtime.h>

// Problem constants (fixed by the reference): B=8, C=64, H=W=256.
#define Bn   8
#define Cn   64
#define Hn   256
#define Wn   256
#define HWn  (Hn * Wn)          // 65536
#define FULLM 0xFFFFFFFFu
#define TPB  256                // 8 warps: block = 32 pixels x 64 channels

__global__ __launch_bounds__(TPB)
void warp_bilinear_kernel(const float* __restrict__ phi,
                          const float* __restrict__ x_enc,
                          const float* __restrict__ m,
                          float* __restrict__ out)
{
    __shared__ float wgt_s[4][32];      // [corner][rank]
    __shared__ int   off_s[4][32];      // [corner][rank]
    __shared__ int   rank_s[32];        // pixel lane -> rank, -1 if invalid
    __shared__ int   nval_s;
    __shared__ float res_s[32 * 65];    // [rank][channel], pad 65 (bank-safe)

    const int tid   = threadIdx.x;
    const int lane  = tid & 31;
    const int wslot = tid >> 5;

    const int pixwarp = blockIdx.x;          // 0..16383: 32-pixel group
    const int b       = pixwarp >> 11;       // 2048 groups per batch image
    const int hwg     = (pixwarp & 2047) << 5;

    // ---- Phase 1: warp 0 computes sampling setup ONCE for the 32 pixels ----
    if (wslot == 0) {
        const int hw = hwg + lane;
        const int h  = hw >> 8;
        const int w  = hw & (Wn - 1);

        const float px = phi[(b * 2 + 0) * HWn + hw];
        const float py = phi[(b * 2 + 1) * HWn + hw];
        const float mv = m[b * HWn + hw];

        // vgrid = 2*(coord+phi)/(dim-1) - 1 + 2*phi ; unnormalize (align_corners=False)
        const float vx = 2.0f * ((float)w + px) / (float)(Wn - 1) - 1.0f + 2.0f * px;
        const float vy = 2.0f * ((float)h + py) / (float)(Hn - 1) - 1.0f + 2.0f * py;
        const float ix = (vx + 1.0f) * (0.5f * (float)Wn) - 0.5f;
        const float iy = (vy + 1.0f) * (0.5f * (float)Hn) - 0.5f;

        const float x0f = floorf(ix);
        const float y0f = floorf(iy);
        const int   x0  = (int)x0f;
        const int   y0  = (int)y0f;
        const int   x1  = x0 + 1;
        const int   y1  = y0 + 1;

        const float wx1 = ix - x0f;
        const float wx0 = 1.0f - wx1;
        const float wy1 = iy - y0f;
        const float wy0 = 1.0f - wy1;

        const float vx0 = (x0 >= 0 && x0 < Wn) ? 1.0f : 0.0f;
        const float vx1 = (x1 >= 0 && x1 < Wn) ? 1.0f : 0.0f;
        const float vy0 = (y0 >= 0 && y0 < Hn) ? 1.0f : 0.0f;
        const float vy1 = (y1 >= 0 && y1 < Hn) ? 1.0f : 0.0f;

        // Fold validity AND mask into corner weights (zeros padding, out *= m)
        const float w00 = wy0 * wx0 * vy0 * vx0 * mv;
        const float w01 = wy0 * wx1 * vy0 * vx1 * mv;
        const float w10 = wy1 * wx0 * vy1 * vx0 * mv;
        const float w11 = wy1 * wx1 * vy1 * vx1 * mv;

        const int x0c = min(max(x0, 0), Wn - 1);
        const int x1c = min(max(x1, 0), Wn - 1);
        const int y0c = min(max(y0, 0), Hn - 1);
        const int y1c = min(max(y1, 0), Hn - 1);

        const bool pvalid = (w00 != 0.0f) | (w01 != 0.0f) |
                            (w10 != 0.0f) | (w11 != 0.0f);
        const unsigned blt = __ballot_sync(FULLM, pvalid);
        const int rank = __popc(blt & ((1u << lane) - 1u));

        rank_s[lane] = pvalid ? rank : -1;
        if (pvalid) {
            wgt_s[0][rank] = w00;  off_s[0][rank] = y0c * Wn + x0c;
            wgt_s[1][rank] = w01;  off_s[1][rank] = y0c * Wn + x1c;
            wgt_s[2][rank] = w10;  off_s[2][rank] = y1c * Wn + x0c;
            wgt_s[3][rank] = w11;  off_s[3][rank] = y1c * Wn + x1c;
        }
        if (lane == 0) nval_s = __popc(blt);
    }
    __syncthreads();

    const int k     = nval_s;
    const int baseB = b * Cn * HWn;
    const float4 z  = make_float4(0.0f, 0.0f, 0.0f, 0.0f);
    const int q     = (tid & 7) << 2;             // this thread's pixel quad

    // ---- Fast path (31% of blocks): no valid pixels -> pure zero stores,
    // no smem reads, no second barrier. ----
    if (k == 0) {
#pragma unroll
        for (int rd = 0; rd < 2; ++rd) {
            const int ch = (tid >> 3) + (rd << 5);
            __stcs((float4*)(out + baseB + ch * HWn + hwg + q), z);
        }
        return;
    }

    const int r0 = rank_s[q + 0];
    const int r1 = rank_s[q + 1];
    const int r2 = rank_s[q + 2];
    const int r3 = rank_s[q + 3];
    const bool quad_valid = (r0 >= 0) | (r1 >= 0) | (r2 >= 0) | (r3 >= 0);

    // ---- Phase 3a (hoisted): zero stores for all-invalid quads (~86%).
    // Independent of the gather -> issues/drains DURING gather latency. ----
    if (!quad_valid) {
#pragma unroll
        for (int rd = 0; rd < 2; ++rd) {
            const int ch = (tid >> 3) + (rd << 5);
            __stcs((float4*)(out + baseB + ch * HWn + hwg + q), z);
        }
    }

    // ---- Phase 2: block-wide gather, task = (valid pixel rank, channel) ----
    {
        const int ntask = k << 6;                 // k * 64 channels
        for (int t = tid; t < ntask; t += TPB) {
            const int j  = t >> 6;                // rank
            const int ch = t & 63;
            const float W00 = wgt_s[0][j];
            const float W01 = wgt_s[1][j];
            const float W10 = wgt_s[2][j];
            const float W11 = wgt_s[3][j];
            const int   O00 = off_s[0][j];
            const int   O01 = off_s[1][j];
            const int   O10 = off_s[2][j];
            const int   O11 = off_s[3][j];
            const float* __restrict__ pc = x_enc + baseB + ch * HWn;
            float a = 0.0f, bv = 0.0f, cv = 0.0f, dv = 0.0f;
            if (W00 != 0.0f) a  = __ldg(pc + O00);
            if (W01 != 0.0f) bv = __ldg(pc + O01);
            if (W10 != 0.0f) cv = __ldg(pc + O10);
            if (W11 != 0.0f) dv = __ldg(pc + O11);
            res_s[j * 65 + ch] =
                fmaf(W00, a, fmaf(W01, bv, fmaf(W10, cv, W11 * dv)));
        }
    }
    __syncthreads();

    // ---- Phase 3b: stores for quads containing >=1 valid pixel only. ----
    if (quad_valid) {
#pragma unroll
        for (int rd = 0; rd < 2; ++rd) {
            const int ch = (tid >> 3) + (rd << 5);    // 0..63
            float4 v;
            v.x = (r0 >= 0) ? res_s[r0 * 65 + ch] : 0.0f;
            v.y = (r1 >= 0) ? res_s[r1 * 65 + ch] : 0.0f;
            v.z = (r2 >= 0) ? res_s[r2 * 65 + ch] : 0.0f;
            v.w = (r3 >= 0) ? res_s[r3 * 65 + ch] : 0.0f;
            __stcs((float4*)(out + baseB + ch * HWn + hwg + q), v);
        }
    }
}

extern "C" void kernel_launch(void* const* d_in, const int* in_sizes, int n_in,
                              void* d_out, int out_size)
{
    const float* phi   = (const float*)d_in[0];
    const float* x_enc = (const float*)d_in[1];
    const float* m     = (const float*)d_in[2];
    float* out         = (float*)d_out;

    const int blocks = (Bn * HWn) / 32;    // 16384 pixel-groups
    warp_bilinear_kernel<<<blocks, TPB>>>(phi, x_enc, m, out);
}

// round 14
// speedup vs baseline: 1.8187x; 1.1356x over previous
#include <cuda_runtime.h>

// Problem constants (fixed by the reference): B=8, C=64, H=W=256.
#define Bn   8
#define Cn   64
#define Hn   256
#define Wn   256
#define HWn  (Hn * Wn)          // 65536
#define FULLM 0xFFFFFFFFu
#define TPB  256                // 8 warps: block = 32 pixels x 64 channels

__global__ __launch_bounds__(TPB)
void warp_bilinear_kernel(const float* __restrict__ phi,
                          const float* __restrict__ x_enc,
                          const float* __restrict__ m,
                          float* __restrict__ out)
{
    __shared__ float4 wgt4_s[32];       // per rank: (w00,w01,w10,w11)
    __shared__ int4   off4_s[32];       // per rank: (o00,o01,o10,o11)
    __shared__ int    rank_s[32];       // pixel lane -> rank, -1 if invalid
    __shared__ int    nval_s;
    __shared__ float  res_s[32 * 65];   // [rank][channel], pad 65 (bank-safe)

    const int tid   = threadIdx.x;
    const int lane  = tid & 31;
    const int wslot = tid >> 5;

    const int pixwarp = blockIdx.x;          // 0..16383: 32-pixel group
    const int b       = pixwarp >> 11;       // 2048 groups per batch image
    const int hwg     = (pixwarp & 2047) << 5;

    // ---- Phase 1: warp 0 computes sampling setup ONCE for the 32 pixels ----
    if (wslot == 0) {
        const int hw = hwg + lane;
        const int h  = hw >> 8;
        const int w  = hw & (Wn - 1);

        const float px = phi[(b * 2 + 0) * HWn + hw];
        const float py = phi[(b * 2 + 1) * HWn + hw];
        const float mv = m[b * HWn + hw];

        // vgrid = 2*(coord+phi)/(dim-1) - 1 + 2*phi ; unnormalize (align_corners=False)
        const float vx = 2.0f * ((float)w + px) / (float)(Wn - 1) - 1.0f + 2.0f * px;
        const float vy = 2.0f * ((float)h + py) / (float)(Hn - 1) - 1.0f + 2.0f * py;
        const float ix = (vx + 1.0f) * (0.5f * (float)Wn) - 0.5f;
        const float iy = (vy + 1.0f) * (0.5f * (float)Hn) - 0.5f;

        const float x0f = floorf(ix);
        const float y0f = floorf(iy);
        const int   x0  = (int)x0f;
        const int   y0  = (int)y0f;
        const int   x1  = x0 + 1;
        const int   y1  = y0 + 1;

        const float wx1 = ix - x0f;
        const float wx0 = 1.0f - wx1;
        const float wy1 = iy - y0f;
        const float wy0 = 1.0f - wy1;

        const float vx0 = (x0 >= 0 && x0 < Wn) ? 1.0f : 0.0f;
        const float vx1 = (x1 >= 0 && x1 < Wn) ? 1.0f : 0.0f;
        const float vy0 = (y0 >= 0 && y0 < Hn) ? 1.0f : 0.0f;
        const float vy1 = (y1 >= 0 && y1 < Hn) ? 1.0f : 0.0f;

        // Fold validity AND mask into corner weights (zeros padding, out *= m)
        const float w00 = wy0 * wx0 * vy0 * vx0 * mv;
        const float w01 = wy0 * wx1 * vy0 * vx1 * mv;
        const float w10 = wy1 * wx0 * vy1 * vx0 * mv;
        const float w11 = wy1 * wx1 * vy1 * vx1 * mv;

        const int x0c = min(max(x0, 0), Wn - 1);
        const int x1c = min(max(x1, 0), Wn - 1);
        const int y0c = min(max(y0, 0), Hn - 1);
        const int y1c = min(max(y1, 0), Hn - 1);

        const bool pvalid = (w00 != 0.0f) | (w01 != 0.0f) |
                            (w10 != 0.0f) | (w11 != 0.0f);
        const unsigned blt = __ballot_sync(FULLM, pvalid);
        const int rank = __popc(blt & ((1u << lane) - 1u));

        rank_s[lane] = pvalid ? rank : -1;
        if (pvalid) {
            wgt4_s[rank] = make_float4(w00, w01, w10, w11);
            off4_s[rank] = make_int4(y0c * Wn + x0c, y0c * Wn + x1c,
                                     y1c * Wn + x0c, y1c * Wn + x1c);
        }
        if (lane == 0) nval_s = __popc(blt);
    }
    __syncthreads();

    const int k     = nval_s;
    const int baseB = b * Cn * HWn;
    const int q     = (tid & 7) << 2;             // this thread's pixel quad

    // ---- Fast path (31% of blocks): no valid pixels -> warp-uniform zero
    // stores, no gather, no second barrier. ----
    if (k == 0) {
        const float4 z = make_float4(0.0f, 0.0f, 0.0f, 0.0f);
#pragma unroll
        for (int rd = 0; rd < 2; ++rd) {
            const int ch = (tid >> 3) + (rd << 5);
            __stcs((float4*)(out + baseB + ch * HWn + hwg + q), z);
        }
        return;
    }

    // Hoisted rank reads (only depend on barrier 1).
    const int r0 = rank_s[q + 0];
    const int r1 = rank_s[q + 1];
    const int r2 = rank_s[q + 2];
    const int r3 = rank_s[q + 3];

    // ---- Phase 2: block-wide gather, task = (valid pixel rank, channel) ----
    {
        const int ntask = k << 6;                 // k * 64 channels
        for (int t = tid; t < ntask; t += TPB) {
            const int j  = t >> 6;                // rank
            const int ch = t & 63;
            const float4 W = wgt4_s[j];           // one LDS.128
            const int4   O = off4_s[j];           // one LDS.128
            const float* __restrict__ pc = x_enc + baseB + ch * HWn;
            float a = 0.0f, bv = 0.0f, cv = 0.0f, dv = 0.0f;
            if (W.x != 0.0f) a  = __ldg(pc + O.x);
            if (W.y != 0.0f) bv = __ldg(pc + O.y);
            if (W.z != 0.0f) cv = __ldg(pc + O.z);
            if (W.w != 0.0f) dv = __ldg(pc + O.w);
            res_s[j * 65 + ch] =
                fmaf(W.x, a, fmaf(W.y, bv, fmaf(W.z, cv, W.w * dv)));
        }
    }
    __syncthreads();

    // ---- Phase 3 (unified, R7 structure): every thread stores its 2 quads;
    // full-warp waves -> contiguous 128B store lines. ----
#pragma unroll
    for (int rd = 0; rd < 2; ++rd) {
        const int ch = (tid >> 3) + (rd << 5);    // 0..63
        float4 v;
        v.x = (r0 >= 0) ? res_s[r0 * 65 + ch] : 0.0f;
        v.y = (r1 >= 0) ? res_s[r1 * 65 + ch] : 0.0f;
        v.z = (r2 >= 0) ? res_s[r2 * 65 + ch] : 0.0f;
        v.w = (r3 >= 0) ? res_s[r3 * 65 + ch] : 0.0f;
        __stcs((float4*)(out + baseB + ch * HWn + hwg + q), v);
    }
}

extern "C" void kernel_launch(void* const* d_in, const int* in_sizes, int n_in,
                              void* d_out, int out_size)
{
    const float* phi   = (const float*)d_in[0];
    const float* x_enc = (const float*)d_in[1];
    const float* m     = (const float*)d_in[2];
    float* out         = (float*)d_out;

    const int blocks = (Bn * HWn) / 32;    // 16384 pixel-groups
    warp_bilinear_kernel<<<blocks, TPB>>>(phi, x_enc, m, out);
}